// round 2
// baseline (speedup 1.0000x reference)
#include <cuda_runtime.h>
#include <cstdint>
#include <cstddef>

// ============================================================================
// DPLSTMCell on GB300 via classic mma.sync (sm_103 plain target — no 'a'
// features available in this harness's nvcc invocation, so no tcgen05/TMEM).
//
//   gates[8192, 4096] = X[8192,1024] @ W_ih^T + Hp[8192,1024] @ W_hh^T + b
//   tf32 m16n8k8 mma.sync, fp32 accumulate, cp.async 3-stage pipeline.
//   CTA tile 128(M) x 128(N); N-tile gate-packed = 4 gates x 32 h-indices,
//   so the LSTM pointwise epilogue is fully fused (no gates scratch in HBM).
// ============================================================================

#define KC 32
#define NCHUNK 64            // K = 2048 / 32
#define STAGES 3
#define LDA 36               // smem row stride in floats (32 + 4 pad)
#define MAT_FLOATS (128 * LDA)               // one 128x32 tile, padded
#define STAGE_BYTES (2 * MAT_FLOATS * 4)     // A + B per stage = 36864 B
#define OFF_BIAS 0                            // 128 floats
#define OFF_STAGE 1024
#define SMEM_TOTAL (OFF_STAGE + STAGES * STAGE_BYTES)   // 111616 B
#define GLDA 132             // epilogue staging row stride (floats)

__device__ __forceinline__ uint32_t smem_u32_(const void* p) {
    uint32_t a;
    asm("{ .reg .u64 t; cvta.to.shared.u64 t, %1; cvt.u32.u64 %0, t; }" : "=r"(a) : "l"(p));
    return a;
}
__device__ __forceinline__ void cp16(uint32_t s, const void* g) {
    asm volatile("cp.async.cg.shared.global [%0], [%1], 16;" :: "r"(s), "l"(g) : "memory");
}

#define MMA_TF32(c, a, b)                                                     \
    asm volatile(                                                             \
        "mma.sync.aligned.m16n8k8.row.col.f32.tf32.tf32.f32 "                 \
        "{%0,%1,%2,%3}, {%4,%5,%6,%7}, {%8,%9}, {%0,%1,%2,%3};"               \
        : "+f"((c)[0]), "+f"((c)[1]), "+f"((c)[2]), "+f"((c)[3])              \
        : "r"(__float_as_uint((a)[0])), "r"(__float_as_uint((a)[1])),         \
          "r"(__float_as_uint((a)[2])), "r"(__float_as_uint((a)[3])),         \
          "r"(__float_as_uint((b)[0])), "r"(__float_as_uint((b)[1])))

__device__ __forceinline__ float sig_(float x) {
    x = fminf(fmaxf(x, -30.f), 30.f);
    return __fdividef(1.f, 1.f + __expf(-x));
}
__device__ __forceinline__ float th_(float x) {
    x = fminf(fmaxf(x, -15.f), 15.f);
    float e = __expf(-2.f * x);
    return __fdividef(1.f - e, 1.f + e);
}

__global__ void __launch_bounds__(256, 2)
lstm_cell_kernel(const float* __restrict__ X, const float* __restrict__ Hp,
                 const float* __restrict__ Cp,
                 const float* __restrict__ Wih, const float* __restrict__ bih,
                 const float* __restrict__ Whh, const float* __restrict__ bhh,
                 float* __restrict__ out) {
    extern __shared__ char smem[];
    const uint32_t sb = smem_u32_(smem);
    const int tid = threadIdx.x;
    const int wid = tid >> 5;
    const int lane = tid & 31;
    const int g8 = lane >> 2;        // group id 0..7
    const int qc = lane & 3;         // quad col 0..3
    const int warpM = (wid >> 2) * 64;   // 2 warps along M
    const int warpN = (wid & 3) * 32;    // 4 warps along N
    const int h0 = blockIdx.x * 32;      // 32 h-indices per CTA (x = n-tile for L2)
    const int m0 = blockIdx.y * 128;     // batch tile

    float* bias_s = (float*)(smem + OFF_BIAS);
    // combined bias for this n-tile: col c = gate(c>>5)*32 + j(c&31)
    if (tid < 128) {
        int gr = ((tid >> 5) << 10) + h0 + (tid & 31);
        bias_s[tid] = bih[gr] + bhh[gr];
    }

    // ---- chunk loader: A 128x32 (batch rows) + B 128x32 (gate-packed W rows)
    auto issue_chunk = [&](int k, int s) {
        int kk = k << 5;
        const float* Ag; const float* Wg; int ko;
        if (kk < 1024) { Ag = X;  Wg = Wih; ko = kk; }
        else           { Ag = Hp; Wg = Whh; ko = kk - 1024; }
        uint32_t abase = sb + OFF_STAGE + s * STAGE_BYTES;
        uint32_t bbase = abase + MAT_FLOATS * 4;
        #pragma unroll
        for (int t = 0; t < 4; t++) {
            int sid = tid + t * 256;           // 1024 16B segments
            int r = sid >> 3, c = sid & 7;
            cp16(abase + (r * LDA + c * 4) * 4,
                 Ag + (((size_t)(m0 + r)) << 10) + ko + (c << 2));
        }
        #pragma unroll
        for (int t = 0; t < 4; t++) {
            int sid = tid + t * 256;
            int r = sid >> 3, c = sid & 7;
            int wr = ((r >> 5) << 10) + h0 + (r & 31);   // gate*1024 + h0 + j
            cp16(bbase + (r * LDA + c * 4) * 4,
                 Wg + (((size_t)wr) << 10) + ko + (c << 2));
        }
        asm volatile("cp.async.commit_group;" ::: "memory");
    };

    float acc[4][4][4];
    #pragma unroll
    for (int mf = 0; mf < 4; mf++)
        #pragma unroll
        for (int nf = 0; nf < 4; nf++)
            #pragma unroll
            for (int e = 0; e < 4; e++) acc[mf][nf][e] = 0.f;

    // ---- prologue: 2 chunks in flight ----
    issue_chunk(0, 0);
    issue_chunk(1, 1);

    // ---- mainloop ----
    for (int k = 0; k < NCHUNK; k++) {
        int s = k % STAGES;
        if (k < NCHUNK - 1) asm volatile("cp.async.wait_group 1;" ::: "memory");
        else                asm volatile("cp.async.wait_group 0;" ::: "memory");
        __syncthreads();
        if (k + 2 < NCHUNK) issue_chunk(k + 2, (k + 2) % STAGES);

        const float* As = (const float*)(smem + OFF_STAGE + s * STAGE_BYTES);
        const float* Bs = As + MAT_FLOATS;
        #pragma unroll
        for (int ks = 0; ks < 4; ks++) {
            int k0 = ks * 8;
            float a[4][4];
            #pragma unroll
            for (int mf = 0; mf < 4; mf++) {
                const float* ap = As + (warpM + mf * 16 + g8) * LDA + k0 + qc;
                a[mf][0] = ap[0];
                a[mf][1] = ap[8 * LDA];
                a[mf][2] = ap[4];
                a[mf][3] = ap[8 * LDA + 4];
            }
            float b[4][2];
            #pragma unroll
            for (int nf = 0; nf < 4; nf++) {
                const float* bp = Bs + (warpN + nf * 8 + g8) * LDA + k0 + qc;
                b[nf][0] = bp[0];
                b[nf][1] = bp[4];
            }
            #pragma unroll
            for (int mf = 0; mf < 4; mf++)
                #pragma unroll
                for (int nf = 0; nf < 4; nf++)
                    MMA_TF32(acc[mf][nf], a[mf], b[nf]);
        }
        __syncthreads();   // protect stage buffer before reuse by issue at k+? (slot rotation)
    }

    // ---- epilogue: stage gates 128x128 to SMEM (reuse pipeline buffers) ----
    float* gbuf = (float*)(smem + OFF_STAGE);
    #pragma unroll
    for (int mf = 0; mf < 4; mf++) {
        #pragma unroll
        for (int nf = 0; nf < 4; nf++) {
            int row = warpM + mf * 16 + g8;
            int col = warpN + nf * 8 + 2 * qc;
            float2* p0 = (float2*)(gbuf + row * GLDA + col);
            float2* p1 = (float2*)(gbuf + (row + 8) * GLDA + col);
            *p0 = make_float2(acc[mf][nf][0], acc[mf][nf][1]);
            *p1 = make_float2(acc[mf][nf][2], acc[mf][nf][3]);
        }
    }
    __syncthreads();

    float* outH = out;
    float* outC = out + ((size_t)8192 * 1024);
    const int j = tid & 31;
    #pragma unroll
    for (int i = 0; i < 16; i++) {
        int r = (tid >> 5) + 8 * i;          // 0..127
        const float* gr = gbuf + r * GLDA + j;
        float xi = gr[0]  + bias_s[j];
        float xf = gr[32] + bias_s[32 + j];
        float xg = gr[64] + bias_s[64 + j];
        float xo = gr[96] + bias_s[96 + j];
        size_t off = (((size_t)(m0 + r)) << 10) + h0 + j;
        float cpv = Cp[off];
        float it = sig_(xi), ft = sig_(xf);
        float gt = th_(xg),  ot = sig_(xo);
        float ct = ft * cpv + it * gt;
        float ht = ot * th_(ct);
        outH[off] = ht;
        outC[off] = ct;
    }
}

extern "C" void kernel_launch(void* const* d_in, const int* in_sizes, int n_in,
                              void* d_out, int out_size) {
    (void)in_sizes; (void)n_in; (void)out_size;
    cudaFuncSetAttribute(lstm_cell_kernel,
                         cudaFuncAttributeMaxDynamicSharedMemorySize, SMEM_TOTAL);
    dim3 grid(32, 64);   // x = n-tiles (h), y = m-tiles (batch)
    lstm_cell_kernel<<<grid, 256, SMEM_TOTAL>>>(
        (const float*)d_in[0], (const float*)d_in[1], (const float*)d_in[2],
        (const float*)d_in[3], (const float*)d_in[4],
        (const float*)d_in[5], (const float*)d_in[6],
        (float*)d_out);
}

// round 3
// speedup vs baseline: 2.3339x; 2.3339x over previous
#include <cuda_runtime.h>
#include <cuda_fp16.h>
#include <cstdint>
#include <cstddef>

// ============================================================================
// DPLSTMCell on GB300 (plain sm_103 target — no tcgen05 in this harness).
// Round 3: fp16 mma.sync m16n8k16 (2x tf32 MAC rate, same 11-bit mantissa),
// ldmatrix.x4 operand loads, XOR-swizzled smem, single barrier per k-chunk.
//   Pass 1: convert X, Hp, W_ih, W_hh fp32 -> fp16 scratch (64 MB static).
//   Pass 2: gates = [X|Hp] @ [Wih|Whh]^T + b, fused LSTM epilogue.
// ============================================================================

#define ARRN 8388608                       // 8192*1024 elements per array
__device__ __align__(256) __half g_scr[4ull * ARRN];   // Xh, Hph, Wih_h, Whh_h

// ---------------- conversion kernel ----------------
__global__ void __launch_bounds__(256)
cvt4_kernel(const float4* __restrict__ a, const float4* __restrict__ b,
            const float4* __restrict__ c, const float4* __restrict__ d) {
    const float4* src = (blockIdx.y == 0) ? a : (blockIdx.y == 1) ? b
                       : (blockIdx.y == 2) ? c : d;
    __half* dst = g_scr + (size_t)blockIdx.y * ARRN;
    int i = blockIdx.x * blockDim.x + threadIdx.x;   // 8 floats per thread
    float4 f0 = src[2 * i], f1 = src[2 * i + 1];
    union { __half h[8]; uint4 u; } p;
    p.h[0] = __float2half_rn(f0.x); p.h[1] = __float2half_rn(f0.y);
    p.h[2] = __float2half_rn(f0.z); p.h[3] = __float2half_rn(f0.w);
    p.h[4] = __float2half_rn(f1.x); p.h[5] = __float2half_rn(f1.y);
    p.h[6] = __float2half_rn(f1.z); p.h[7] = __float2half_rn(f1.w);
    ((uint4*)dst)[i] = p.u;
}

// ---------------- GEMM + LSTM kernel ----------------
#define NCHUNK 32            // K = 2048 / 64
#define STAGES 3
#define A_TILE_BYTES 16384   // 128 rows x 128 B (64 halves)
#define STAGE_BYTES  32768   // A + B
#define OFF_BIAS 0
#define OFF_STAGE 1024
#define SMEM_TOTAL (OFF_STAGE + STAGES * STAGE_BYTES)   // 99328
#define GLDA 132             // fp32 epilogue staging row stride

__device__ __forceinline__ uint32_t smem_u32_(const void* p) {
    uint32_t a;
    asm("{ .reg .u64 t; cvta.to.shared.u64 t, %1; cvt.u32.u64 %0, t; }" : "=r"(a) : "l"(p));
    return a;
}
__device__ __forceinline__ void cp16(uint32_t s, const void* g) {
    asm volatile("cp.async.cg.shared.global [%0], [%1], 16;" :: "r"(s), "l"(g) : "memory");
}
#define LDSM_X4(r, addr)                                                      \
    asm volatile("ldmatrix.sync.aligned.m8n8.x4.shared.b16 {%0,%1,%2,%3}, [%4];" \
        : "=r"((r)[0]), "=r"((r)[1]), "=r"((r)[2]), "=r"((r)[3]) : "r"(addr))
#define MMA_F16(c, a, b)                                                      \
    asm volatile(                                                             \
        "mma.sync.aligned.m16n8k16.row.col.f32.f16.f16.f32 "                  \
        "{%0,%1,%2,%3}, {%4,%5,%6,%7}, {%8,%9}, {%0,%1,%2,%3};"               \
        : "+f"((c)[0]), "+f"((c)[1]), "+f"((c)[2]), "+f"((c)[3])              \
        : "r"((a)[0]), "r"((a)[1]), "r"((a)[2]), "r"((a)[3]),                 \
          "r"((b)[0]), "r"((b)[1]))

__device__ __forceinline__ float sig_(float x) {
    x = fminf(fmaxf(x, -30.f), 30.f);
    return __fdividef(1.f, 1.f + __expf(-x));
}
__device__ __forceinline__ float th_(float x) {
    x = fminf(fmaxf(x, -15.f), 15.f);
    float e = __expf(-2.f * x);
    return __fdividef(1.f - e, 1.f + e);
}

__global__ void __launch_bounds__(256, 2)
lstm_gemm_kernel(const float* __restrict__ Cp,
                 const float* __restrict__ bih, const float* __restrict__ bhh,
                 float* __restrict__ out) {
    extern __shared__ char smem[];
    const uint32_t sb = smem_u32_(smem);
    const int tid = threadIdx.x;
    const int wid = tid >> 5;
    const int lane = tid & 31;
    const int g8 = lane >> 2;
    const int qc = lane & 3;
    const int warpM = (wid >> 2) * 64;
    const int warpN = (wid & 3) * 32;
    const int h0 = blockIdx.x * 32;
    const int m0 = blockIdx.y * 128;

    const __half* Xh   = g_scr;
    const __half* Hph  = g_scr + (size_t)ARRN;
    const __half* WihH = g_scr + (size_t)2 * ARRN;
    const __half* WhhH = g_scr + (size_t)3 * ARRN;

    float* bias_s = (float*)(smem + OFF_BIAS);
    if (tid < 128) {
        int gr = ((tid >> 5) << 10) + h0 + (tid & 31);
        bias_s[tid] = bih[gr] + bhh[gr];
    }

    // ---- chunk loader: A 128x64h + B 128x64h, 16B segs, XOR swizzle ----
    auto issue_chunk = [&](int k, int s) {
        int kk = k << 6;
        const __half* Ag; const __half* Wg; int ko;
        if (kk < 1024) { Ag = Xh;  Wg = WihH; ko = kk; }
        else           { Ag = Hph; Wg = WhhH; ko = kk - 1024; }
        uint32_t abase = sb + OFF_STAGE + s * STAGE_BYTES;
        uint32_t bbase = abase + A_TILE_BYTES;
        #pragma unroll
        for (int t = 0; t < 4; t++) {
            int sid = tid + t * 256;             // 1024 segs
            int r = sid >> 3, c = sid & 7;
            uint32_t so = r * 128 + ((c ^ (r & 7)) << 4);
            cp16(abase + so, Ag + (((size_t)(m0 + r)) << 10) + ko + (c << 3));
        }
        #pragma unroll
        for (int t = 0; t < 4; t++) {
            int sid = tid + t * 256;
            int r = sid >> 3, c = sid & 7;
            int wr = ((r >> 5) << 10) + h0 + (r & 31);   // gate*1024 + h0 + j
            uint32_t so = r * 128 + ((c ^ (r & 7)) << 4);
            cp16(bbase + so, Wg + (((size_t)wr) << 10) + ko + (c << 3));
        }
        asm volatile("cp.async.commit_group;" ::: "memory");
    };

    float acc[4][4][4];
    #pragma unroll
    for (int mf = 0; mf < 4; mf++)
        #pragma unroll
        for (int nf = 0; nf < 4; nf++)
            #pragma unroll
            for (int e = 0; e < 4; e++) acc[mf][nf][e] = 0.f;

    // ldmatrix per-lane invariants
    const int a_l15 = lane & 15, a_hi = lane >> 4;             // A: rows, k-half
    const int b_nrl = (lane & 7) + ((lane >> 4) << 3);         // B: n-offset
    const int b_hi  = (lane >> 3) & 1;                          // B: k-half

    issue_chunk(0, 0);
    issue_chunk(1, 1);

    for (int k = 0; k < NCHUNK; k++) {
        int s = k % STAGES;
        if (k < NCHUNK - 1) asm volatile("cp.async.wait_group 1;" ::: "memory");
        else                asm volatile("cp.async.wait_group 0;" ::: "memory");
        __syncthreads();
        if (k + 2 < NCHUNK) issue_chunk(k + 2, (k + 2) % STAGES);

        uint32_t As = sb + OFF_STAGE + s * STAGE_BYTES;
        uint32_t Bs = As + A_TILE_BYTES;
        #pragma unroll
        for (int ks = 0; ks < 4; ks++) {
            uint32_t a[4][4];
            #pragma unroll
            for (int mf = 0; mf < 4; mf++) {
                int row = warpM + mf * 16 + a_l15;
                uint32_t addr = As + row * 128 + (((2 * ks + a_hi) ^ (row & 7)) << 4);
                LDSM_X4(a[mf], addr);
            }
            uint32_t b[2][4];
            #pragma unroll
            for (int nfp = 0; nfp < 2; nfp++) {
                int row = warpN + nfp * 16 + b_nrl;
                uint32_t addr = Bs + row * 128 + (((2 * ks + b_hi) ^ (row & 7)) << 4);
                LDSM_X4(b[nfp], addr);
            }
            #pragma unroll
            for (int mf = 0; mf < 4; mf++)
                #pragma unroll
                for (int nf = 0; nf < 4; nf++)
                    MMA_F16(acc[mf][nf], a[mf], b[nf >> 1] + (nf & 1) * 2);
        }
    }

    // ---- epilogue: stage 128x128 fp32 gates to smem, fused LSTM pointwise ----
    __syncthreads();
    float* gbuf = (float*)(smem + OFF_STAGE);
    #pragma unroll
    for (int mf = 0; mf < 4; mf++) {
        #pragma unroll
        for (int nf = 0; nf < 4; nf++) {
            int row = warpM + mf * 16 + g8;
            int col = warpN + nf * 8 + 2 * qc;
            *(float2*)(gbuf + row * GLDA + col)       = make_float2(acc[mf][nf][0], acc[mf][nf][1]);
            *(float2*)(gbuf + (row + 8) * GLDA + col) = make_float2(acc[mf][nf][2], acc[mf][nf][3]);
        }
    }
    __syncthreads();

    float* outH = out;
    float* outC = out + ((size_t)8192 * 1024);
    const int j = lane;
    #pragma unroll
    for (int i = 0; i < 16; i++) {
        int r = wid + 8 * i;
        const float* gr = gbuf + r * GLDA + j;
        float xi = gr[0]  + bias_s[j];
        float xf = gr[32] + bias_s[32 + j];
        float xg = gr[64] + bias_s[64 + j];
        float xo = gr[96] + bias_s[96 + j];
        size_t off = (((size_t)(m0 + r)) << 10) + h0 + j;
        float cpv = Cp[off];
        float it = sig_(xi), ft = sig_(xf);
        float gt = th_(xg),  ot = sig_(xo);
        float ct = ft * cpv + it * gt;
        float ht = ot * th_(ct);
        outH[off] = ht;
        outC[off] = ct;
    }
}

extern "C" void kernel_launch(void* const* d_in, const int* in_sizes, int n_in,
                              void* d_out, int out_size) {
    (void)in_sizes; (void)n_in; (void)out_size;
    // Pass 1: fp32 -> fp16 (X, Hp, Wih, Whh)
    dim3 cgrid(ARRN / (256 * 8), 4);
    cvt4_kernel<<<cgrid, 256>>>(
        (const float4*)d_in[0], (const float4*)d_in[1],
        (const float4*)d_in[3], (const float4*)d_in[5]);
    // Pass 2: GEMM + LSTM
    cudaFuncSetAttribute(lstm_gemm_kernel,
                         cudaFuncAttributeMaxDynamicSharedMemorySize, SMEM_TOTAL);
    dim3 grid(32, 64);
    lstm_gemm_kernel<<<grid, 256, SMEM_TOTAL>>>(
        (const float*)d_in[2], (const float*)d_in[4], (const float*)d_in[6],
        (float*)d_out);
}